// round 1
// baseline (speedup 1.0000x reference)
#include <cuda_runtime.h>

// LIF neuron recurrence, fully parallel across B*N neurons, serial over T.
//   out[t]  = (mem > 1.0f) ? 1 : 0
//   mem     = (0.5f*mem + syn) * (1 - out[t])
//   syn     = in[t]
// inputs: [T, B, N] fp32 contiguous; output same shape.

__global__ void __launch_bounds__(256) lif_kernel(
    const float4* __restrict__ in,
    float4* __restrict__ out,
    int T, int n4)
{
    int i = blockIdx.x * blockDim.x + threadIdx.x;
    if (i >= n4) return;

    float4 mem = make_float4(0.f, 0.f, 0.f, 0.f);
    float4 syn = make_float4(0.f, 0.f, 0.f, 0.f);

    size_t idx = (size_t)i;
    const size_t stride = (size_t)n4;

    #pragma unroll 4
    for (int t = 0; t < T; ++t, idx += stride) {
        float4 x = in[idx];

        float4 o;
        o.x = (mem.x > 1.0f) ? 1.0f : 0.0f;
        o.y = (mem.y > 1.0f) ? 1.0f : 0.0f;
        o.z = (mem.z > 1.0f) ? 1.0f : 0.0f;
        o.w = (mem.w > 1.0f) ? 1.0f : 0.0f;

        out[idx] = o;

        mem.x = (0.5f * mem.x + syn.x) * (1.0f - o.x);
        mem.y = (0.5f * mem.y + syn.y) * (1.0f - o.y);
        mem.z = (0.5f * mem.z + syn.z) * (1.0f - o.z);
        mem.w = (0.5f * mem.w + syn.w) * (1.0f - o.w);

        syn = x;
    }
}

extern "C" void kernel_launch(void* const* d_in, const int* in_sizes, int n_in,
                              void* d_out, int out_size)
{
    const float* in = (const float*)d_in[0];
    float* out = (float*)d_out;

    const int T = 100;                 // fixed by problem shape [100, 256, 2048]
    const int BN = in_sizes[0] / T;    // 524288
    const int n4 = BN / 4;             // 131072 float4 lanes

    const int threads = 256;
    const int blocks = (n4 + threads - 1) / threads;  // 512

    lif_kernel<<<blocks, threads>>>(
        (const float4*)in, (float4*)out, T, n4);
}

// round 2
// speedup vs baseline: 1.0162x; 1.0162x over previous
#include <cuda_runtime.h>

// LIF neuron recurrence, fully parallel across B*N neurons, serial over T.
//   out[t]  = (mem > 1.0f) ? 1 : 0
//   mem     = (0.5f*mem + syn) * (1 - out[t])
//   syn     = in[t]
// inputs: [T, B, N] fp32 contiguous; output same shape.
//
// R2: block=128 (grid=1024) to fix CTA->SM quantization (512 blocks gave
// 4-vs-3 CTA imbalance -> 84% max chip util). Streaming cache hints since
// data is touched exactly once (419MB stream vs 126MB L2).

__global__ void __launch_bounds__(128) lif_kernel(
    const float4* __restrict__ in,
    float4* __restrict__ out,
    int T, int n4)
{
    int i = blockIdx.x * blockDim.x + threadIdx.x;
    if (i >= n4) return;

    float4 mem = make_float4(0.f, 0.f, 0.f, 0.f);
    float4 syn = make_float4(0.f, 0.f, 0.f, 0.f);

    size_t idx = (size_t)i;
    const size_t stride = (size_t)n4;

    #pragma unroll 4
    for (int t = 0; t < T; ++t, idx += stride) {
        float4 x = __ldcs(&in[idx]);   // evict-first: no reuse

        float4 o;
        o.x = (mem.x > 1.0f) ? 1.0f : 0.0f;
        o.y = (mem.y > 1.0f) ? 1.0f : 0.0f;
        o.z = (mem.z > 1.0f) ? 1.0f : 0.0f;
        o.w = (mem.w > 1.0f) ? 1.0f : 0.0f;

        __stcs(&out[idx], o);          // streaming store

        mem.x = (0.5f * mem.x + syn.x) * (1.0f - o.x);
        mem.y = (0.5f * mem.y + syn.y) * (1.0f - o.y);
        mem.z = (0.5f * mem.z + syn.z) * (1.0f - o.z);
        mem.w = (0.5f * mem.w + syn.w) * (1.0f - o.w);

        syn = x;
    }
}

extern "C" void kernel_launch(void* const* d_in, const int* in_sizes, int n_in,
                              void* d_out, int out_size)
{
    const float* in = (const float*)d_in[0];
    float* out = (float*)d_out;

    const int T = 100;                 // fixed by problem shape [100, 256, 2048]
    const int BN = in_sizes[0] / T;    // 524288
    const int n4 = BN / 4;             // 131072 float4 lanes

    const int threads = 128;
    const int blocks = (n4 + threads - 1) / threads;  // 1024

    lif_kernel<<<blocks, threads>>>(
        (const float4*)in, (float4*)out, T, n4);
}